// round 4
// baseline (speedup 1.0000x reference)
#include <cuda_runtime.h>
#include <math.h>

#define B_  64
#define C_  512
#define HW_ 4096      // 64*64
#define E_  16
#define K_  4

__device__ float g_pooled[B_ * C_];
__device__ int   g_count[B_];      // zero-init; each replay returns it to 0

// ---------------------------------------------------------------------------
// Fused kernel: pool every (b,c) row; the warp that completes a batch's 512th
// row computes the full gate for that batch (overlapped with other pooling).
// One warp per (b,c) row. 8 warps / 256 threads per block; a block's 8 rows
// always belong to the same batch (512 rows per batch), so at most one gate
// warp per block -> block-shared scratch is safe.
// ---------------------------------------------------------------------------
__global__ __launch_bounds__(256) void fused_gate_kernel(
    const float* __restrict__ x,
    const float* __restrict__ W0, const float* __restrict__ b0,
    const float* __restrict__ W1, const float* __restrict__ b1,
    float* __restrict__ out) {

    const int row  = (blockIdx.x * blockDim.x + threadIdx.x) >> 5;  // (b,c) in [0, B*C)
    const int lane = threadIdx.x & 31;
    const int b    = row >> 9;                                      // row / 512

    __shared__ float sh_h[E_];
    __shared__ float sh_n[E_];

    // ---------------- pool: max + mean over 4096 contiguous floats ----------
    const float4* __restrict__ p =
        reinterpret_cast<const float4*>(x + (size_t)row * HW_);

    float mx0 = -INFINITY, mx1 = -INFINITY;
    float sm0 = 0.0f, sm1 = 0.0f;
#pragma unroll
    for (int i = 0; i < HW_ / 4 / 32; i += 2) {   // 32 float4 per lane, 2 chains
        float4 a = p[i * 32 + lane];
        float4 c = p[(i + 1) * 32 + lane];
        mx0 = fmaxf(mx0, fmaxf(fmaxf(a.x, a.y), fmaxf(a.z, a.w)));
        sm0 += (a.x + a.y) + (a.z + a.w);
        mx1 = fmaxf(mx1, fmaxf(fmaxf(c.x, c.y), fmaxf(c.z, c.w)));
        sm1 += (c.x + c.y) + (c.z + c.w);
    }
    float mx = fmaxf(mx0, mx1);
    float sm = sm0 + sm1;
#pragma unroll
    for (int o = 16; o; o >>= 1) {
        mx = fmaxf(mx, __shfl_xor_sync(0xffffffffu, mx, o));
        sm += __shfl_xor_sync(0xffffffffu, sm, o);
    }

    // publish + completion count (threadfence-reduction pattern)
    int last = 0;
    if (lane == 0) {
        g_pooled[row] = mx + sm * (1.0f / HW_);
        __threadfence();
        last = (atomicAdd(&g_count[b], 1) == C_ - 1);
    }
    last = __shfl_sync(0xffffffffu, last, 0);
    if (!last) return;

    __threadfence();   // acquire: make all 512 g_pooled writes visible

    // ---------------- gate for batch b (single warp) ------------------------
    const float4* __restrict__ prow =
        reinterpret_cast<const float4*>(g_pooled + b * C_);
    float4 pv[4];
#pragma unroll
    for (int i = 0; i < 4; i++) pv[i] = prow[lane + 32 * i];

#pragma unroll
    for (int e = 0; e < E_; e++) {
        const float4* __restrict__ w0p =
            reinterpret_cast<const float4*>(W0 + e * C_);
        const float4* __restrict__ w1p =
            reinterpret_cast<const float4*>(W1 + e * C_);
        float d0 = 0.0f, d1 = 0.0f;
#pragma unroll
        for (int i = 0; i < 4; i++) {
            float4 w0 = w0p[lane + 32 * i];
            float4 w1 = w1p[lane + 32 * i];
            d0 = fmaf(pv[i].x, w0.x, d0); d0 = fmaf(pv[i].y, w0.y, d0);
            d0 = fmaf(pv[i].z, w0.z, d0); d0 = fmaf(pv[i].w, w0.w, d0);
            d1 = fmaf(pv[i].x, w1.x, d1); d1 = fmaf(pv[i].y, w1.y, d1);
            d1 = fmaf(pv[i].z, w1.z, d1); d1 = fmaf(pv[i].w, w1.w, d1);
        }
#pragma unroll
        for (int o = 16; o; o >>= 1) {
            d0 += __shfl_xor_sync(0xffffffffu, d0, o);
            d1 += __shfl_xor_sync(0xffffffffu, d1, o);
        }
        if (lane == 0) {
            float hv = d0 + b0[e];
            sh_h[e] = (hv >= 0.0f) ? hv : 0.2f * hv;                 // LeakyReLU
            float z = d1 + b1[e];
            sh_n[e] = fmaxf(z, 0.0f) + log1pf(expf(-fabsf(z)));      // softplus
        }
    }
    __syncwarp();

    // ---------------- scalar epilogue on lane 0 -----------------------------
    if (lane == 0) {
        float h[E_], nz[E_];
#pragma unroll
        for (int i = 0; i < E_; i++) { h[i] = sh_h[i]; nz[i] = sh_n[i]; }

        float mu = 0.0f;
#pragma unroll
        for (int i = 0; i < E_; i++) mu += nz[i];
        mu *= (1.0f / E_);

        float var = 0.0f;
#pragma unroll
        for (int i = 0; i < E_; i++) { float d = nz[i] - mu; var += d * d; }
        float sd = sqrtf(var * (1.0f / (E_ - 1)));       // ddof=1

        float score[E_];
#pragma unroll
        for (int i = 0; i < E_; i++) score[i] = h[i] + (nz[i] - mu) / sd;

        // top-K; strict '>' = first-occurrence tie-break like jax.lax.top_k
        bool sel[E_];
#pragma unroll
        for (int i = 0; i < E_; i++) sel[i] = false;
        for (int k = 0; k < K_; k++) {
            int   best = -1;
            float bv   = -INFINITY;
#pragma unroll
            for (int i = 0; i < E_; i++) {
                if (!sel[i] && score[i] > bv) { bv = score[i]; best = i; }
            }
            sel[best] = true;
        }

        float mh = -INFINITY;
#pragma unroll
        for (int i = 0; i < E_; i++) if (sel[i]) mh = fmaxf(mh, h[i]);
        float s = 0.0f;
        float g[E_];
#pragma unroll
        for (int i = 0; i < E_; i++) {
            g[i] = sel[i] ? expf(h[i] - mh) : 0.0f;
            s += g[i];
        }
        float inv = 1.0f / s;
#pragma unroll
        for (int i = 0; i < E_; i++) out[b * E_ + i] = g[i] * inv;

        g_count[b] = 0;   // reset for next graph replay (deterministic)
    }
}

// ---------------------------------------------------------------------------
extern "C" void kernel_launch(void* const* d_in, const int* in_sizes, int n_in,
                              void* d_out, int out_size) {
    const float* x  = (const float*)d_in[0];
    const float* W0 = (const float*)d_in[1];
    const float* b0 = (const float*)d_in[2];
    const float* W1 = (const float*)d_in[3];
    const float* b1 = (const float*)d_in[4];
    float* out = (float*)d_out;

    fused_gate_kernel<<<(B_ * C_) / 8, 256>>>(x, W0, b0, W1, b1, out);
}

// round 5
// speedup vs baseline: 1.2183x; 1.2183x over previous
#include <cuda_runtime.h>
#include <math.h>

#define B_  64
#define C_  512
#define HW_ 4096      // 64*64
#define E_  16
#define K_  4

// Scratch for pooled [B, C] (device global — no allocation)
__device__ float g_pooled[B_ * C_];

// ---------------------------------------------------------------------------
// Kernel 1: pooled[b,c] = max(x[b,c,:,:]) + mean(x[b,c,:,:])
// One warp per (b,c) row of 4096 contiguous floats.  HBM-bound; at the roof.
// ---------------------------------------------------------------------------
__global__ __launch_bounds__(256) void pool_kernel(const float* __restrict__ x) {
    const int warp = (blockIdx.x * blockDim.x + threadIdx.x) >> 5;  // row in [0, B*C)
    const int lane = threadIdx.x & 31;

    const float4* __restrict__ p =
        reinterpret_cast<const float4*>(x + (size_t)warp * HW_);

    float mx0 = -INFINITY, mx1 = -INFINITY;
    float sm0 = 0.0f, sm1 = 0.0f;
#pragma unroll
    for (int i = 0; i < HW_ / 4 / 32; i += 2) {   // 32 float4 per lane, 2 chains
        float4 a = p[i * 32 + lane];
        float4 b = p[(i + 1) * 32 + lane];
        mx0 = fmaxf(mx0, fmaxf(fmaxf(a.x, a.y), fmaxf(a.z, a.w)));
        sm0 += (a.x + a.y) + (a.z + a.w);
        mx1 = fmaxf(mx1, fmaxf(fmaxf(b.x, b.y), fmaxf(b.z, b.w)));
        sm1 += (b.x + b.y) + (b.z + b.w);
    }
    float mx = fmaxf(mx0, mx1);
    float sm = sm0 + sm1;
#pragma unroll
    for (int o = 16; o; o >>= 1) {
        mx = fmaxf(mx, __shfl_xor_sync(0xffffffffu, mx, o));
        sm += __shfl_xor_sync(0xffffffffu, sm, o);
    }
    if (lane == 0) {
        g_pooled[warp] = mx + sm * (1.0f / HW_);
    }
    // Signal dependent (PDL) launch: all our writes for consumers are done.
    cudaTriggerProgrammaticLaunchCompletion();
}

// ---------------------------------------------------------------------------
// Kernel 2 (PDL secondary): launches while pool is still running; loads all
// weights into registers first (independent of pool), then grid-dep-syncs,
// then reads the L2-hot pooled row and finishes.
// 64 blocks x 512 threads; warp e handles expert e.
// ---------------------------------------------------------------------------
__global__ __launch_bounds__(512) void gate_kernel(const float* __restrict__ W0,
                                                   const float* __restrict__ b0,
                                                   const float* __restrict__ W1,
                                                   const float* __restrict__ b1,
                                                   float* __restrict__ out) {
    const int b    = blockIdx.x;
    const int tid  = threadIdx.x;
    const int e    = tid >> 5;     // expert = warp id (0..15)
    const int lane = tid & 31;

    __shared__ float sh_h[E_];
    __shared__ float sh_noise[E_];

    // -------- prologue: overlapped with pool_kernel execution --------------
    const float4* __restrict__ w0p =
        reinterpret_cast<const float4*>(W0 + e * C_) + lane;
    const float4* __restrict__ w1p =
        reinterpret_cast<const float4*>(W1 + e * C_) + lane;
    float4 w0r[4], w1r[4];
#pragma unroll
    for (int i = 0; i < 4; i++) w0r[i] = w0p[i * 32];
#pragma unroll
    for (int i = 0; i < 4; i++) w1r[i] = w1p[i * 32];
    const float bias0 = b0[e];
    const float bias1 = b1[e];

    // -------- wait for pool_kernel's g_pooled writes ------------------------
    cudaGridDependencySynchronize();

    const float4* __restrict__ prow =
        reinterpret_cast<const float4*>(g_pooled + b * C_) + lane;
    float d0 = 0.0f, d1 = 0.0f;
#pragma unroll
    for (int i = 0; i < 4; i++) {
        float4 pv = prow[i * 32];
        d0 = fmaf(pv.x, w0r[i].x, d0); d0 = fmaf(pv.y, w0r[i].y, d0);
        d0 = fmaf(pv.z, w0r[i].z, d0); d0 = fmaf(pv.w, w0r[i].w, d0);
        d1 = fmaf(pv.x, w1r[i].x, d1); d1 = fmaf(pv.y, w1r[i].y, d1);
        d1 = fmaf(pv.z, w1r[i].z, d1); d1 = fmaf(pv.w, w1r[i].w, d1);
    }
#pragma unroll
    for (int o = 16; o; o >>= 1) {
        d0 += __shfl_xor_sync(0xffffffffu, d0, o);
        d1 += __shfl_xor_sync(0xffffffffu, d1, o);
    }
    if (lane == 0) {
        float hv = d0 + bias0;
        sh_h[e] = (hv >= 0.0f) ? hv : 0.2f * hv;          // LeakyReLU(0.2)
        float z = d1 + bias1;
        // numerically stable softplus
        sh_noise[e] = fmaxf(z, 0.0f) + log1pf(expf(-fabsf(z)));
    }
    __syncthreads();

    // -------- scalar epilogue: tiny (E=16), single thread per block ---------
    if (tid == 0) {
        float h[E_], nz[E_];
#pragma unroll
        for (int i = 0; i < E_; i++) { h[i] = sh_h[i]; nz[i] = sh_noise[i]; }

        float mu = 0.0f;
#pragma unroll
        for (int i = 0; i < E_; i++) mu += nz[i];
        mu *= (1.0f / E_);

        float var = 0.0f;
#pragma unroll
        for (int i = 0; i < E_; i++) { float d = nz[i] - mu; var += d * d; }
        float sd = sqrtf(var * (1.0f / (E_ - 1)));        // ddof=1

        float score[E_];
#pragma unroll
        for (int i = 0; i < E_; i++) score[i] = h[i] + (nz[i] - mu) / sd;

        // top-K; strict '>' = first-occurrence tie-break like jax.lax.top_k
        bool sel[E_];
#pragma unroll
        for (int i = 0; i < E_; i++) sel[i] = false;
        for (int k = 0; k < K_; k++) {
            int   best = -1;
            float bv   = -INFINITY;
#pragma unroll
            for (int i = 0; i < E_; i++) {
                if (!sel[i] && score[i] > bv) { bv = score[i]; best = i; }
            }
            sel[best] = true;
        }

        float mh = -INFINITY;
#pragma unroll
        for (int i = 0; i < E_; i++) if (sel[i]) mh = fmaxf(mh, h[i]);
        float s = 0.0f;
        float g[E_];
#pragma unroll
        for (int i = 0; i < E_; i++) {
            g[i] = sel[i] ? expf(h[i] - mh) : 0.0f;
            s += g[i];
        }
        float inv = 1.0f / s;
#pragma unroll
        for (int i = 0; i < E_; i++) out[b * E_ + i] = g[i] * inv;
    }
}

// ---------------------------------------------------------------------------
extern "C" void kernel_launch(void* const* d_in, const int* in_sizes, int n_in,
                              void* d_out, int out_size) {
    const float* x  = (const float*)d_in[0];
    const float* W0 = (const float*)d_in[1];
    const float* b0 = (const float*)d_in[2];
    const float* W1 = (const float*)d_in[3];
    const float* b1 = (const float*)d_in[4];
    float* out = (float*)d_out;

    // Primary: pool (8 warps per block, 1 warp per (b,c) row)
    pool_kernel<<<(B_ * C_) / 8, 256>>>(x);

    // Secondary with PDL: starts while pool runs; griddepsync gates the
    // g_pooled consumption.
    cudaLaunchConfig_t cfg = {};
    cfg.gridDim  = dim3(B_, 1, 1);
    cfg.blockDim = dim3(512, 1, 1);
    cfg.dynamicSmemBytes = 0;
    cfg.stream = 0;
    cudaLaunchAttribute attr[1];
    attr[0].id = cudaLaunchAttributeProgrammaticStreamSerialization;
    attr[0].val.programmaticStreamSerializationAllowed = 1;
    cfg.attrs = attr;
    cfg.numAttrs = 1;
    cudaLaunchKernelEx(&cfg, gate_kernel, W0, b0, W1, b1, out);
}